// round 4
// baseline (speedup 1.0000x reference)
#include <cuda_runtime.h>
#include <math.h>
#include <stdint.h>

#define B_    32
#define T_    2048
#define DIN   512
#define D_    256
#define OUTD  41
#define L_    3
#define INNER 512
#define BT    (B_*T_)

// ---------------- scratch ----------------
__device__ float g_h512[(size_t)BT*DIN];
__device__ float g_bufA[(size_t)BT*D_];
__device__ float g_h   [(size_t)BT*D_];
__device__ float g_xz  [(size_t)BT*1024];
__device__ float g_xc  [(size_t)BT*INNER];
__device__ float g_dt  [(size_t)BT*INNER];
__device__ float g_part[B_*INNER*16];
__device__ float g_cat [(size_t)BT*512];
__device__ float g_hout[(size_t)BT*128];
// transposed weights [N][K]
__device__ float g_aWt  [45*512*512];
__device__ float g_cW1t [256*512];
__device__ float g_cW2t [256*256];
__device__ float g_minT [6*1024*256];
__device__ float g_dtWt [6*512*512];
__device__ float g_moutT[6*256*512];
__device__ float g_projT[3*256*512];
__device__ float g_wpadT[128*256];

// ---------------- weight transpose ----------------
__global__ void transp_k(const float* __restrict__ in, float* __restrict__ out,
                         int R, int C)
{
    __shared__ float t[32][33];
    long base = (long)blockIdx.z * R * C;
    int c0 = blockIdx.x*32, r0 = blockIdx.y*32;
    #pragma unroll
    for (int i = 0; i < 32; i += 8)
        t[threadIdx.y + i][threadIdx.x] =
            in[base + (long)(r0 + threadIdx.y + i)*C + c0 + threadIdx.x];
    __syncthreads();
    #pragma unroll
    for (int i = 0; i < 32; i += 8)
        out[base + (long)(c0 + threadIdx.y + i)*R + r0 + threadIdx.x] =
            t[threadIdx.x][threadIdx.y + i];
}

__global__ void wpadT_k(const float* __restrict__ Wo, float* __restrict__ wt)
{
    int idx = blockIdx.x*blockDim.x + threadIdx.x;   // 128*256
    int k = idx & 255, n = idx >> 8;
    wt[n*256 + k] = (n < OUTD) ? Wo[k*OUTD + n] : 0.f;
}

// ---------------- tf32 tensor-core GEMM (ldmatrix fragments) ----------------
#define BM 128
#define BN 128
#define BK 16

__device__ __forceinline__ unsigned s2u(const void* p) {
    return (unsigned)__cvta_generic_to_shared(p);
}
#define CPA(dst, src) asm volatile("cp.async.cg.shared.global [%0], [%1], 16;\n" :: "r"(dst), "l"(src))
#define CP_COMMIT     asm volatile("cp.async.commit_group;\n" ::)
#define CP_WAIT1      asm volatile("cp.async.wait_group 1;\n" ::)
#define CP_WAIT0      asm volatile("cp.async.wait_group 0;\n" ::)
#define LDSMX4(r0,r1,r2,r3,ad) \
    asm volatile("ldmatrix.sync.aligned.m8n8.x4.shared.b16 {%0,%1,%2,%3}, [%4];" \
        : "=r"(r0), "=r"(r1), "=r"(r2), "=r"(r3) : "r"(ad))

// A: [M][K] fp32 (k-contig).  Wt: [N][K] fp32 (k-contig, pre-transposed).
// epi: 0=none, 1=softsign, 2=softplus
__global__ void __launch_bounds__(256, 2) tgemm_k(
    const float* __restrict__ A, int lda, int arev,
    const float* __restrict__ Wt, const float* __restrict__ bias,
    const int* __restrict__ day_ids, long wstride, int bstride,
    float* __restrict__ C, int ldc, int coff, int crev,
    int K, int N, int epi)
{
    __shared__ float As[2][BM][20];
    __shared__ float Bs[2][BN][20];

    int tid  = threadIdx.x;
    int lane = tid & 31;
    int wid  = tid >> 5;
    int wm   = wid & 1;
    int wn   = wid >> 1;
    int n0 = blockIdx.x * BN;
    int m0 = blockIdx.y * BM;

    const float* Wp = Wt;
    const float* bp = bias;
    if (day_ids) {
        int d = day_ids[m0 >> 11];
        Wp += (long)d * wstride;
        if (bp) bp += (long)d * bstride;
    }

    float acc[4][4][4];
    #pragma unroll
    for (int i = 0; i < 4; i++)
        #pragma unroll
        for (int j = 0; j < 4; j++)
            #pragma unroll
            for (int q = 0; q < 4; q++) acc[i][j][q] = 0.f;

    auto load_tiles = [&](int s, int k0) {
        #pragma unroll
        for (int it = 0; it < 2; ++it) {
            int idx = tid + it*256;
            int row = idx >> 2, c4 = (idx & 3) << 2;
            int grow = m0 + row;
            int srow = arev ? ((grow & ~2047) | (2047 - (grow & 2047))) : grow;
            CPA(s2u(&As[s][row][c4]), A + (long)srow*lda + k0 + c4);
        }
        #pragma unroll
        for (int it = 0; it < 2; ++it) {
            int idx = tid + it*256;
            int row = idx >> 2, c4 = (idx & 3) << 2;
            CPA(s2u(&Bs[s][row][c4]), Wp + (long)(n0 + row)*K + k0 + c4);
        }
    };

    // ldmatrix lane addressing: matrix = lane>>3; row-in-matrix = lane&7
    int lrow = (lane & 7) + ((lane >> 3) & 1) * 8;  // +8 rows for matrices 1,3
    int lcol = (lane >> 4) << 2;                     // +4 k-cols for matrices 2,3

    load_tiles(0, 0); CP_COMMIT;
    int s = 0;
    for (int k0 = 0; k0 < K; k0 += BK) {
        bool more = (k0 + BK) < K;
        if (more) { load_tiles(s^1, k0 + BK); CP_COMMIT; CP_WAIT1; }
        else      { CP_WAIT0; }
        __syncthreads();

        #pragma unroll
        for (int kk = 0; kk < 2; ++kk) {
            uint32_t a[4][4], b[2][4];
            #pragma unroll
            for (int mi = 0; mi < 4; ++mi) {
                unsigned ad = s2u(&As[s][wm*64 + mi*16 + lrow][kk*8 + lcol]);
                LDSMX4(a[mi][0], a[mi][1], a[mi][2], a[mi][3], ad);
            }
            #pragma unroll
            for (int np = 0; np < 2; ++np) {
                unsigned ad = s2u(&Bs[s][wn*32 + np*16 + lrow][kk*8 + lcol]);
                LDSMX4(b[np][0], b[np][1], b[np][2], b[np][3], ad);
            }
            #pragma unroll
            for (int mi = 0; mi < 4; ++mi)
                #pragma unroll
                for (int ni = 0; ni < 4; ++ni) {
                    uint32_t b0 = b[ni>>1][ni&1];
                    uint32_t b1 = b[ni>>1][(ni&1)+2];
                    asm volatile(
                        "mma.sync.aligned.m16n8k8.row.col.f32.tf32.tf32.f32 "
                        "{%0,%1,%2,%3}, {%4,%5,%6,%7}, {%8,%9}, {%0,%1,%2,%3};"
                        : "+f"(acc[mi][ni][0]), "+f"(acc[mi][ni][1]),
                          "+f"(acc[mi][ni][2]), "+f"(acc[mi][ni][3])
                        : "r"(a[mi][0]), "r"(a[mi][1]), "r"(a[mi][2]), "r"(a[mi][3]),
                          "r"(b0), "r"(b1));
                }
        }
        __syncthreads();
        s ^= 1;
    }

    #pragma unroll
    for (int ni = 0; ni < 4; ++ni) {
        int col = n0 + wn*32 + ni*8 + ((lane & 3) << 1);
        float b0 = bp ? bp[col]   : 0.f;
        float b1 = bp ? bp[col+1] : 0.f;
        #pragma unroll
        for (int mi = 0; mi < 4; ++mi) {
            #pragma unroll
            for (int half = 0; half < 2; ++half) {
                int grow = m0 + wm*64 + mi*16 + (lane >> 2) + half*8;
                int orow = crev ? ((grow & ~2047) | (2047 - (grow & 2047))) : grow;
                float v0 = acc[mi][ni][half*2+0] + b0;
                float v1 = acc[mi][ni][half*2+1] + b1;
                if (epi == 1) { v0 = v0/(1.f+fabsf(v0)); v1 = v1/(1.f+fabsf(v1)); }
                else if (epi == 2) {
                    v0 = fmaxf(v0,0.f) + log1pf(expf(-fabsf(v0)));
                    v1 = fmaxf(v1,0.f) + log1pf(expf(-fabsf(v1)));
                }
                *(float2*)(C + (long)orow*ldc + coff + col) = make_float2(v0, v1);
            }
        }
    }
}

// ---------------- depthwise conv(4) + SiLU ----------------
__global__ void conv_silu_k(const float* __restrict__ xz,
                            const float* __restrict__ ck,
                            const float* __restrict__ cb,
                            float* __restrict__ xc)
{
    int idx = blockIdx.x*blockDim.x + threadIdx.x;
    int c4  = idx & 127;
    int btt = idx >> 7;
    int t   = btt & 2047;
    int c   = c4 << 2;
    const float* base = xz + (long)btt*1024 + c;
    float4 vm2 = (t >= 2)    ? *(const float4*)(base - 2048) : make_float4(0,0,0,0);
    float4 vm1 = (t >= 1)    ? *(const float4*)(base - 1024) : make_float4(0,0,0,0);
    float4 v0  =               *(const float4*)(base);
    float4 vp1 = (t <= 2046) ? *(const float4*)(base + 1024) : make_float4(0,0,0,0);
    float4 bias = *(const float4*)(cb + c);
    float o[4];
    const float* km2 = (const float*)&vm2;
    const float* km1 = (const float*)&vm1;
    const float* k0p = (const float*)&v0;
    const float* kp1 = (const float*)&vp1;
    const float* bi  = (const float*)&bias;
    #pragma unroll
    for (int i = 0; i < 4; ++i) {
        float4 kk = *(const float4*)(ck + (c+i)*4);
        float sv = bi[i] + km2[i]*kk.x + km1[i]*kk.y + k0p[i]*kk.z + kp1[i]*kk.w;
        o[i] = sv * __fdividef(1.f, 1.f + __expf(-sv));
    }
    *(float4*)(xc + (long)btt*512 + c) = make_float4(o[0],o[1],o[2],o[3]);
}

// ---------------- chunked scan ----------------
__global__ void scan1_k(const float* __restrict__ dt, float* __restrict__ part)
{
    int idx = blockIdx.x*blockDim.x + threadIdx.x;
    int c4 = idx & 127, chunk = (idx >> 7) & 15, b = idx >> 11;
    int c = c4 << 2;
    const float* p = dt + ((long)(b*2048 + chunk*128))*512 + c;
    float4 sv = make_float4(0,0,0,0);
    #pragma unroll 4
    for (int i = 0; i < 128; i++) {
        float4 v = *(const float4*)(p + (long)i*512);
        sv.x += v.x; sv.y += v.y; sv.z += v.z; sv.w += v.w;
    }
    long base = ((long)(b*512 + c) << 4) + chunk;
    part[base] = sv.x; part[base+16] = sv.y; part[base+32] = sv.z; part[base+48] = sv.w;
}

__global__ void scan2_k(float* __restrict__ part)
{
    int idx = blockIdx.x*blockDim.x + threadIdx.x;
    float* p = part + idx*16;
    float sv = 0.f;
    #pragma unroll
    for (int ch = 0; ch < 16; ++ch) { float t = p[ch]; p[ch] = sv; sv += t; }
}

__global__ void scan3_k(const float* __restrict__ dt, const float* __restrict__ xz,
                        float* __restrict__ xc, const float* __restrict__ part)
{
    int idx = blockIdx.x*blockDim.x + threadIdx.x;
    int c4 = idx & 127, chunk = (idx >> 7) & 15, b = idx >> 11;
    int c = c4 << 2;
    long pb = ((long)(b*512 + c) << 4) + chunk;
    float4 accv = make_float4(part[pb], part[pb+16], part[pb+32], part[pb+48]);
    long base  = ((long)(b*2048 + chunk*128))*512  + c;
    long zbase = ((long)(b*2048 + chunk*128))*1024 + 512 + c;
    #pragma unroll 4
    for (int i = 0; i < 128; i++) {
        float4 d = *(const float4*)(dt + base);
        float4 z = *(const float4*)(xz + zbase);
        float4 u = *(const float4*)(xc + base);
        accv.x += d.x; accv.y += d.y; accv.z += d.z; accv.w += d.w;
        float o[4];
        float* ap = (float*)&accv; float* zp = (float*)&z; float* up = (float*)&u;
        #pragma unroll
        for (int q = 0; q < 4; ++q) {
            float w  = __expf(-0.1f * ap[q]);
            float sz = zp[q] * __fdividef(1.f, 1.f + __expf(-zp[q]));
            o[q] = up[q] * w * sz;
        }
        *(float4*)(xc + base) = make_float4(o[0],o[1],o[2],o[3]);
        base += 512; zbase += 1024;
    }
}

// ---------------- warp-per-row LayerNorm ----------------
__device__ __forceinline__ float warp_sum(float v) {
    #pragma unroll
    for (int o = 16; o; o >>= 1) v += __shfl_xor_sync(0xffffffffu, v, o);
    return v;
}

__global__ void ln_k(const float* __restrict__ X, const float* __restrict__ R,
                     const float* __restrict__ s, const float* __restrict__ bb,
                     float* __restrict__ Y, int do_silu)
{
    int w = threadIdx.x >> 5, lane = threadIdx.x & 31;
    long row = (long)blockIdx.x*8 + w;
    const float* xp = X + row*256;
    float v[8];
    #pragma unroll
    for (int q = 0; q < 2; q++) {
        float4 t = *(const float4*)(xp + q*128 + lane*4);
        v[q*4+0]=t.x; v[q*4+1]=t.y; v[q*4+2]=t.z; v[q*4+3]=t.w;
    }
    if (R) {
        const float* rp = R + row*256;
        #pragma unroll
        for (int q = 0; q < 2; q++) {
            float4 t = *(const float4*)(rp + q*128 + lane*4);
            v[q*4+0]+=t.x; v[q*4+1]+=t.y; v[q*4+2]+=t.z; v[q*4+3]+=t.w;
        }
    }
    float sum = 0.f;
    #pragma unroll
    for (int i = 0; i < 8; i++) sum += v[i];
    float m = warp_sum(sum) * (1.f/256.f);
    float sq = 0.f;
    #pragma unroll
    for (int i = 0; i < 8; i++) { float d = v[i]-m; sq += d*d; }
    float inv = rsqrtf(warp_sum(sq)*(1.f/256.f) + 1e-5f);
    float* yp = Y + row*256;
    #pragma unroll
    for (int q = 0; q < 2; q++) {
        int col = q*128 + lane*4;
        float4 sc = *(const float4*)(s + col);
        float4 bc = *(const float4*)(bb + col);
        float o[4];
        #pragma unroll
        for (int i = 0; i < 4; i++) {
            float y = (v[q*4+i]-m)*inv * ((float*)&sc)[i] + ((float*)&bc)[i];
            if (do_silu) y = y * __fdividef(1.f, 1.f + __expf(-y));
            o[i] = y;
        }
        *(float4*)(yp + col) = make_float4(o[0],o[1],o[2],o[3]);
    }
}

// ---------------- head log-softmax ----------------
__global__ void lsm_k(const float* __restrict__ HP, const float* __restrict__ bo,
                      float* __restrict__ out)
{
    int w = threadIdx.x >> 5, lane = threadIdx.x & 31;
    long row = (long)blockIdx.x*8 + w;
    const float* hp = HP + row*128;
    float v0 = hp[lane] + bo[lane];
    float v1 = (lane < 9) ? hp[lane+32] + bo[lane+32] : -INFINITY;
    float mx = fmaxf(v0, v1);
    #pragma unroll
    for (int o = 16; o; o >>= 1) mx = fmaxf(mx, __shfl_xor_sync(0xffffffffu, mx, o));
    float se = __expf(v0 - mx) + (lane < 9 ? __expf(v1 - mx) : 0.f);
    se = warp_sum(se);
    float lse = mx + logf(se);
    out[row*OUTD + lane] = v0 - lse;
    if (lane < 9) out[row*OUTD + lane + 32] = v1 - lse;
}

// ---------------- host ----------------
extern "C" void kernel_launch(void* const* d_in, const int* in_sizes, int n_in,
                              void* d_out, int out_size)
{
    (void)in_sizes; (void)n_in; (void)out_size;
    const float* x         = (const float*)d_in[0];
    const int*   day_ids   = (const int*)  d_in[1];
    const float* adapter_W = (const float*)d_in[2];
    const float* adapter_b = (const float*)d_in[3];
    const float* cW1   = (const float*)d_in[4];
    const float* cb1   = (const float*)d_in[5];
    const float* cln1s = (const float*)d_in[6];
    const float* cln1b = (const float*)d_in[7];
    const float* cW2   = (const float*)d_in[8];
    const float* cb2   = (const float*)d_in[9];
    const float* cln2s = (const float*)d_in[10];
    const float* cln2b = (const float*)d_in[11];
    const float* m_in    = (const float*)d_in[12];
    const float* m_convK = (const float*)d_in[13];
    const float* m_convB = (const float*)d_in[14];
    const float* m_dtW   = (const float*)d_in[15];
    const float* m_dtB   = (const float*)d_in[16];
    const float* m_out   = (const float*)d_in[17];
    const float* proj_W  = (const float*)d_in[18];
    const float* proj_b  = (const float*)d_in[19];
    const float* norm_s  = (const float*)d_in[20];
    const float* norm_b  = (const float*)d_in[21];
    const float* outW    = (const float*)d_in[22];
    const float* outb    = (const float*)d_in[23];
    float* out = (float*)d_out;

    static float *p_h512=nullptr, *p_bufA=nullptr, *p_h=nullptr, *p_xz=nullptr,
                 *p_xc=nullptr, *p_dt=nullptr, *p_part=nullptr, *p_cat=nullptr,
                 *p_hout=nullptr, *p_aWt=nullptr, *p_cW1t=nullptr, *p_cW2t=nullptr,
                 *p_minT=nullptr, *p_dtWt=nullptr, *p_moutT=nullptr, *p_projT=nullptr,
                 *p_wpadT=nullptr;
    if (!p_h512) {
        cudaGetSymbolAddress((void**)&p_h512, g_h512);
        cudaGetSymbolAddress((void**)&p_bufA, g_bufA);
        cudaGetSymbolAddress((void**)&p_h,    g_h);
        cudaGetSymbolAddress((void**)&p_xz,   g_xz);
        cudaGetSymbolAddress((void**)&p_xc,   g_xc);
        cudaGetSymbolAddress((void**)&p_dt,   g_dt);
        cudaGetSymbolAddress((void**)&p_part, g_part);
        cudaGetSymbolAddress((void**)&p_cat,  g_cat);
        cudaGetSymbolAddress((void**)&p_hout, g_hout);
        cudaGetSymbolAddress((void**)&p_aWt,  g_aWt);
        cudaGetSymbolAddress((void**)&p_cW1t, g_cW1t);
        cudaGetSymbolAddress((void**)&p_cW2t, g_cW2t);
        cudaGetSymbolAddress((void**)&p_minT, g_minT);
        cudaGetSymbolAddress((void**)&p_dtWt, g_dtWt);
        cudaGetSymbolAddress((void**)&p_moutT, g_moutT);
        cudaGetSymbolAddress((void**)&p_projT, g_projT);
        cudaGetSymbolAddress((void**)&p_wpadT, g_wpadT);
    }

    // ---- transpose all weights to [N][K] ----
    dim3 tb(32, 8);
    transp_k<<<dim3(512/32, 512/32, 45), tb>>>(adapter_W, p_aWt, 512, 512);
    transp_k<<<dim3(256/32, 512/32, 1),  tb>>>(cW1, p_cW1t, 512, 256);
    transp_k<<<dim3(256/32, 256/32, 1),  tb>>>(cW2, p_cW2t, 256, 256);
    transp_k<<<dim3(1024/32, 256/32, 6), tb>>>(m_in, p_minT, 256, 1024);
    transp_k<<<dim3(512/32, 512/32, 6),  tb>>>(m_dtW, p_dtWt, 512, 512);
    transp_k<<<dim3(256/32, 512/32, 6),  tb>>>(m_out, p_moutT, 512, 256);
    transp_k<<<dim3(256/32, 512/32, 3),  tb>>>(proj_W, p_projT, 512, 256);
    wpadT_k<<<128, 256>>>(outW, p_wpadT);

    auto gemm = [&](const float* A, int lda, int arev,
                    const float* Wt, const float* bias,
                    const int* days, long wstride, int bstride,
                    float* C, int ldc, int coff, int crev,
                    int K, int N, int epi) {
        dim3 grid(N/BN, BT/BM);
        tgemm_k<<<grid, 256>>>(A, lda, arev, Wt, bias, days, wstride, bstride,
                               C, ldc, coff, crev, K, N, epi);
    };

    // 1) adapter
    gemm(x, 512, 0, p_aWt, adapter_b, day_ids, 512L*512, 512,
         p_h512, 512, 0, 0, 512, 512, 1);
    // 2) stem
    gemm(p_h512, 512, 0, p_cW1t, cb1, nullptr,0,0, p_bufA, 256, 0,0, 512, 256, 0);
    ln_k<<<BT/8, 256>>>(p_bufA, nullptr, cln1s, cln1b, p_h, 1);
    gemm(p_h, 256, 0, p_cW2t, cb2, nullptr,0,0, p_bufA, 256, 0,0, 256, 256, 0);
    ln_k<<<BT/8, 256>>>(p_bufA, nullptr, cln2s, cln2b, p_h, 1);

    // 3) layers
    for (int l = 0; l < L_; ++l) {
        for (int dir = 0; dir < 2; ++dir) {
            int pi = l*2 + dir;
            const float* WinT  = p_minT  + (long)pi*1024*256;
            const float* ck    = m_convK + (long)pi*512*4;
            const float* cb    = m_convB + (long)pi*512;
            const float* dtWT  = p_dtWt  + (long)pi*512*512;
            const float* dtB   = m_dtB   + (long)pi*512;
            const float* WoutT = p_moutT + (long)pi*256*512;

            gemm(p_h, 256, dir, WinT, nullptr, nullptr,0,0,
                 p_xz, 1024, 0, 0, 256, 1024, 0);
            conv_silu_k<<<(BT*128)/256, 256>>>(p_xz, ck, cb, p_xc);
            gemm(p_xc, 512, 0, dtWT, dtB, nullptr,0,0,
                 p_dt, 512, 0, 0, 512, 512, 2);
            scan1_k<<<256, 256>>>(p_dt, p_part);
            scan2_k<<<64, 256>>>(p_part);
            scan3_k<<<256, 256>>>(p_dt, p_xz, p_xc, p_part);
            gemm(p_xc, 512, 0, WoutT, nullptr, nullptr,0,0,
                 p_cat, 512, dir*256, dir, 512, 256, 0);
        }
        gemm(p_cat, 512, 0, p_projT + (long)l*256*512, proj_b + l*256,
             nullptr,0,0, p_bufA, 256, 0,0, 512, 256, 0);
        ln_k<<<BT/8, 256>>>(p_bufA, p_h, norm_s + l*256, norm_b + l*256, p_h, 0);
    }

    // 4) head
    gemm(p_h, 256, 0, p_wpadT, nullptr, nullptr,0,0, p_hout, 128, 0,0, 256, 128, 0);
    lsm_k<<<BT/8, 256>>>(p_hout, outb, out);
}

// round 5
// speedup vs baseline: 1.1428x; 1.1428x over previous
#include <cuda_runtime.h>
#include <math.h>
#include <stdint.h>

#define B_    32
#define T_    2048
#define DIN   512
#define D_    256
#define OUTD  41
#define L_    3
#define INNER 512
#define BT    (B_*T_)

// ---------------- scratch ----------------
__device__ float g_h512[(size_t)BT*DIN];
__device__ float g_bufA[(size_t)BT*D_];
__device__ float g_h   [(size_t)BT*D_];
__device__ float g_xz  [(size_t)BT*1024];
__device__ float g_xc  [(size_t)BT*INNER];
__device__ float g_dt  [(size_t)BT*INNER];
__device__ float g_part[B_*INNER*16];
__device__ float g_cat [(size_t)BT*512];
__device__ float g_wpad[256*128];
__device__ float g_hout[(size_t)BT*128];

// ---------------- tf32 tensor-core GEMM (3-stage cp.async) ----------------
#define BM 128
#define BN 128
#define BK 16
#define ASTRIDE 20
#define BSTRIDE 136
#define SMEM_BYTES ((3*BM*ASTRIDE + 3*BK*BSTRIDE)*4)

__device__ __forceinline__ unsigned s2u(const void* p) {
    return (unsigned)__cvta_generic_to_shared(p);
}
#define CPA(dst, src) asm volatile("cp.async.cg.shared.global [%0], [%1], 16;\n" :: "r"(dst), "l"(src))
#define CP_COMMIT     asm volatile("cp.async.commit_group;\n" ::)
#define CP_WAIT1      asm volatile("cp.async.wait_group 1;\n" ::)
#define CP_WAIT0      asm volatile("cp.async.wait_group 0;\n" ::)

// epi: 0=none, 1=softsign, 2=softplus, 3=softplus + fused per-chunk column sums
__global__ void __launch_bounds__(256, 2) tgemm_k(
    const float* __restrict__ A, int lda, int arev,
    const float* __restrict__ W, const float* __restrict__ bias,
    const int* __restrict__ day_ids, long wstride, int bstride,
    float* __restrict__ C, int ldc, int coff, int crev,
    int K, int N, int epi, float* __restrict__ part)
{
    extern __shared__ float sm[];
    float (*As)[BM][ASTRIDE]  = (float(*)[BM][ASTRIDE])sm;
    float (*Bs)[BK][BSTRIDE]  = (float(*)[BK][BSTRIDE])(sm + 3*BM*ASTRIDE);
    __shared__ float sred[256];

    int tid  = threadIdx.x;
    int lane = tid & 31;
    int wid  = tid >> 5;
    int wm   = wid & 1;
    int wn   = wid >> 1;
    int n0 = blockIdx.x * BN;
    int m0 = blockIdx.y * BM;

    const float* Wp = W;
    const float* bp = bias;
    if (day_ids) {
        int d = day_ids[m0 >> 11];
        Wp += (long)d * wstride;
        if (bp) bp += (long)d * bstride;
    }

    float acc[4][4][4];
    #pragma unroll
    for (int i = 0; i < 4; i++)
        #pragma unroll
        for (int j = 0; j < 4; j++)
            #pragma unroll
            for (int q = 0; q < 4; q++) acc[i][j][q] = 0.f;

    auto load_tiles = [&](int s, int k0) {
        #pragma unroll
        for (int it = 0; it < 2; ++it) {
            int idx = tid + it*256;
            int row = idx >> 2, c4 = (idx & 3) << 2;
            int grow = m0 + row;
            int srow = arev ? ((grow & ~2047) | (2047 - (grow & 2047))) : grow;
            CPA(s2u(&As[s][row][c4]), A + (long)srow*lda + k0 + c4);
        }
        #pragma unroll
        for (int it = 0; it < 2; ++it) {
            int idx = tid + it*256;
            int kr = idx >> 5, nc = (idx & 31) << 2;
            CPA(s2u(&Bs[s][kr][nc]), Wp + (long)(k0+kr)*N + n0 + nc);
        }
    };

    load_tiles(0, 0); CP_COMMIT;
    load_tiles(1, BK); CP_COMMIT;

    int s = 0;
    for (int k0 = 0; k0 < K; k0 += BK) {
        if (k0 + BK < K) { CP_WAIT1; } else { CP_WAIT0; }
        __syncthreads();
        if (k0 + 2*BK < K) {
            int ws = s + 2; if (ws >= 3) ws -= 3;
            load_tiles(ws, k0 + 2*BK); CP_COMMIT;
        }

        #pragma unroll
        for (int kk = 0; kk < 2; ++kk) {
            int kq = kk*8 + (lane & 3);
            uint32_t af[4][4], bf[4][2];
            #pragma unroll
            for (int mi = 0; mi < 4; ++mi) {
                int r = wm*64 + mi*16 + (lane >> 2);
                af[mi][0] = __float_as_uint(As[s][r  ][kq  ]);
                af[mi][1] = __float_as_uint(As[s][r+8][kq  ]);
                af[mi][2] = __float_as_uint(As[s][r  ][kq+4]);
                af[mi][3] = __float_as_uint(As[s][r+8][kq+4]);
            }
            #pragma unroll
            for (int ni = 0; ni < 4; ++ni) {
                int c = wn*32 + ni*8 + (lane >> 2);
                bf[ni][0] = __float_as_uint(Bs[s][kq  ][c]);
                bf[ni][1] = __float_as_uint(Bs[s][kq+4][c]);
            }
            #pragma unroll
            for (int mi = 0; mi < 4; ++mi)
                #pragma unroll
                for (int ni = 0; ni < 4; ++ni)
                    asm volatile(
                        "mma.sync.aligned.m16n8k8.row.col.f32.tf32.tf32.f32 "
                        "{%0,%1,%2,%3}, {%4,%5,%6,%7}, {%8,%9}, {%0,%1,%2,%3};"
                        : "+f"(acc[mi][ni][0]), "+f"(acc[mi][ni][1]),
                          "+f"(acc[mi][ni][2]), "+f"(acc[mi][ni][3])
                        : "r"(af[mi][0]), "r"(af[mi][1]), "r"(af[mi][2]), "r"(af[mi][3]),
                          "r"(bf[ni][0]), "r"(bf[ni][1]));
        }
        s = (s + 1 >= 3) ? 0 : s + 1;
    }

    float csum[4][2];
    #pragma unroll
    for (int ni = 0; ni < 4; ++ni) { csum[ni][0] = 0.f; csum[ni][1] = 0.f; }

    #pragma unroll
    for (int ni = 0; ni < 4; ++ni) {
        int col = n0 + wn*32 + ni*8 + ((lane & 3) << 1);
        float b0 = bp ? bp[col]   : 0.f;
        float b1 = bp ? bp[col+1] : 0.f;
        #pragma unroll
        for (int mi = 0; mi < 4; ++mi) {
            #pragma unroll
            for (int half = 0; half < 2; ++half) {
                int grow = m0 + wm*64 + mi*16 + (lane >> 2) + half*8;
                int orow = crev ? ((grow & ~2047) | (2047 - (grow & 2047))) : grow;
                float v0 = acc[mi][ni][half*2+0] + b0;
                float v1 = acc[mi][ni][half*2+1] + b1;
                if (epi == 1) { v0 = v0/(1.f+fabsf(v0)); v1 = v1/(1.f+fabsf(v1)); }
                else if (epi >= 2) {
                    v0 = fmaxf(v0,0.f) + log1pf(expf(-fabsf(v0)));
                    v1 = fmaxf(v1,0.f) + log1pf(expf(-fabsf(v1)));
                }
                if (epi == 3) { csum[ni][0] += v0; csum[ni][1] += v1; }
                *(float2*)(C + (long)orow*ldc + coff + col) = make_float2(v0, v1);
            }
        }
    }

    // fused scan1: per-chunk (=per-BM-tile) column sums -> part
    if (epi == 3) {
        #pragma unroll
        for (int ni = 0; ni < 4; ++ni)
            #pragma unroll
            for (int q = 0; q < 2; ++q)
                #pragma unroll
                for (int o = 4; o < 32; o <<= 1)
                    csum[ni][q] += __shfl_xor_sync(0xffffffffu, csum[ni][q], o);
        if ((lane >> 2) == 0) {
            #pragma unroll
            for (int ni = 0; ni < 4; ++ni)
                #pragma unroll
                for (int q = 0; q < 2; ++q)
                    sred[(((wm*4 + wn)*4 + ni)*4 + lane)*2 + q] = csum[ni][q];
        }
        __syncthreads();
        if (wm == 0 && (lane >> 2) == 0) {
            int b = m0 >> 11, chunk = (m0 >> 7) & 15;
            #pragma unroll
            for (int ni = 0; ni < 4; ++ni)
                #pragma unroll
                for (int q = 0; q < 2; ++q) {
                    int c = n0 + wn*32 + ni*8 + lane*2 + q;
                    float tot = sred[((wn*4 + ni)*4 + lane)*2 + q]
                              + sred[(((4 + wn)*4 + ni)*4 + lane)*2 + q];
                    part[((long)(b*512 + c) << 4) + chunk] = tot;
                }
        }
    }
}

// ---------------- depthwise conv(4) + SiLU ----------------
__global__ void conv_silu_k(const float* __restrict__ xz,
                            const float* __restrict__ ck,
                            const float* __restrict__ cb,
                            float* __restrict__ xc)
{
    int idx = blockIdx.x*blockDim.x + threadIdx.x;
    int c4  = idx & 127;
    int btt = idx >> 7;
    int t   = btt & 2047;
    int c   = c4 << 2;
    const float* base = xz + (long)btt*1024 + c;
    float4 vm2 = (t >= 2)    ? *(const float4*)(base - 2048) : make_float4(0,0,0,0);
    float4 vm1 = (t >= 1)    ? *(const float4*)(base - 1024) : make_float4(0,0,0,0);
    float4 v0  =               *(const float4*)(base);
    float4 vp1 = (t <= 2046) ? *(const float4*)(base + 1024) : make_float4(0,0,0,0);
    float4 bias = *(const float4*)(cb + c);
    float o[4];
    const float* km2 = (const float*)&vm2;
    const float* km1 = (const float*)&vm1;
    const float* k0p = (const float*)&v0;
    const float* kp1 = (const float*)&vp1;
    const float* bi  = (const float*)&bias;
    #pragma unroll
    for (int i = 0; i < 4; ++i) {
        float4 kk = *(const float4*)(ck + (c+i)*4);
        float sv = bi[i] + km2[i]*kk.x + km1[i]*kk.y + k0p[i]*kk.z + kp1[i]*kk.w;
        o[i] = sv * __fdividef(1.f, 1.f + __expf(-sv));
    }
    *(float4*)(xc + (long)btt*512 + c) = make_float4(o[0],o[1],o[2],o[3]);
}

// ---------------- scan stages 2 & 3 (stage 1 fused into dt GEMM) --------
__global__ void scan2_k(float* __restrict__ part)
{
    int idx = blockIdx.x*blockDim.x + threadIdx.x;
    float* p = part + idx*16;
    float sv = 0.f;
    #pragma unroll
    for (int ch = 0; ch < 16; ++ch) { float t = p[ch]; p[ch] = sv; sv += t; }
}

__global__ void scan3_k(const float* __restrict__ dt, const float* __restrict__ xz,
                        float* __restrict__ xc, const float* __restrict__ part)
{
    int idx = blockIdx.x*blockDim.x + threadIdx.x;
    int c4 = idx & 127, chunk = (idx >> 7) & 15, b = idx >> 11;
    int c = c4 << 2;
    long pb = ((long)(b*512 + c) << 4) + chunk;
    float4 accv = make_float4(part[pb], part[pb+16], part[pb+32], part[pb+48]);
    long base  = ((long)(b*2048 + chunk*128))*512  + c;
    long zbase = ((long)(b*2048 + chunk*128))*1024 + 512 + c;
    #pragma unroll 4
    for (int i = 0; i < 128; i++) {
        float4 d = *(const float4*)(dt + base);
        float4 z = *(const float4*)(xz + zbase);
        float4 u = *(const float4*)(xc + base);
        accv.x += d.x; accv.y += d.y; accv.z += d.z; accv.w += d.w;
        float o[4];
        float* ap = (float*)&accv; float* zp = (float*)&z; float* up = (float*)&u;
        #pragma unroll
        for (int q = 0; q < 4; ++q) {
            float w  = __expf(-0.1f * ap[q]);
            float sz = zp[q] * __fdividef(1.f, 1.f + __expf(-zp[q]));
            o[q] = up[q] * w * sz;
        }
        *(float4*)(xc + base) = make_float4(o[0],o[1],o[2],o[3]);
        base += 512; zbase += 1024;
    }
}

// ---------------- warp-per-row LayerNorm ----------------
__device__ __forceinline__ float warp_sum(float v) {
    #pragma unroll
    for (int o = 16; o; o >>= 1) v += __shfl_xor_sync(0xffffffffu, v, o);
    return v;
}

__global__ void ln_k(const float* __restrict__ X, const float* __restrict__ R,
                     const float* __restrict__ s, const float* __restrict__ bb,
                     float* __restrict__ Y, int do_silu)
{
    int w = threadIdx.x >> 5, lane = threadIdx.x & 31;
    long row = (long)blockIdx.x*8 + w;
    const float* xp = X + row*256;
    float v[8];
    #pragma unroll
    for (int q = 0; q < 2; q++) {
        float4 t = *(const float4*)(xp + q*128 + lane*4);
        v[q*4+0]=t.x; v[q*4+1]=t.y; v[q*4+2]=t.z; v[q*4+3]=t.w;
    }
    if (R) {
        const float* rp = R + row*256;
        #pragma unroll
        for (int q = 0; q < 2; q++) {
            float4 t = *(const float4*)(rp + q*128 + lane*4);
            v[q*4+0]+=t.x; v[q*4+1]+=t.y; v[q*4+2]+=t.z; v[q*4+3]+=t.w;
        }
    }
    float sum = 0.f;
    #pragma unroll
    for (int i = 0; i < 8; i++) sum += v[i];
    float m = warp_sum(sum) * (1.f/256.f);
    float sq = 0.f;
    #pragma unroll
    for (int i = 0; i < 8; i++) { float d = v[i]-m; sq += d*d; }
    float inv = rsqrtf(warp_sum(sq)*(1.f/256.f) + 1e-5f);
    float* yp = Y + row*256;
    #pragma unroll
    for (int q = 0; q < 2; q++) {
        int col = q*128 + lane*4;
        float4 sc = *(const float4*)(s + col);
        float4 bc = *(const float4*)(bb + col);
        float o[4];
        #pragma unroll
        for (int i = 0; i < 4; i++) {
            float y = (v[q*4+i]-m)*inv * ((float*)&sc)[i] + ((float*)&bc)[i];
            if (do_silu) y = y * __fdividef(1.f, 1.f + __expf(-y));
            o[i] = y;
        }
        *(float4*)(yp + col) = make_float4(o[0],o[1],o[2],o[3]);
    }
}

// ---------------- head: pad W, GEMM, then log-softmax ----------------
__global__ void wpad_k(const float* __restrict__ Wo, float* __restrict__ wpad)
{
    int idx = blockIdx.x*blockDim.x + threadIdx.x;   // 256*128
    int col = idx & 127, row = idx >> 7;
    wpad[idx] = (col < OUTD) ? Wo[row*OUTD + col] : 0.f;
}

__global__ void lsm_k(const float* __restrict__ HP, const float* __restrict__ bo,
                      float* __restrict__ out)
{
    int w = threadIdx.x >> 5, lane = threadIdx.x & 31;
    long row = (long)blockIdx.x*8 + w;
    const float* hp = HP + row*128;
    float v0 = hp[lane] + bo[lane];
    float v1 = (lane < 9) ? hp[lane+32] + bo[lane+32] : -INFINITY;
    float mx = fmaxf(v0, v1);
    #pragma unroll
    for (int o = 16; o; o >>= 1) mx = fmaxf(mx, __shfl_xor_sync(0xffffffffu, mx, o));
    float se = __expf(v0 - mx) + (lane < 9 ? __expf(v1 - mx) : 0.f);
    se = warp_sum(se);
    float lse = mx + logf(se);
    out[row*OUTD + lane] = v0 - lse;
    if (lane < 9) out[row*OUTD + lane + 32] = v1 - lse;
}

// ---------------- host ----------------
extern "C" void kernel_launch(void* const* d_in, const int* in_sizes, int n_in,
                              void* d_out, int out_size)
{
    (void)in_sizes; (void)n_in; (void)out_size;
    const float* x         = (const float*)d_in[0];
    const int*   day_ids   = (const int*)  d_in[1];
    const float* adapter_W = (const float*)d_in[2];
    const float* adapter_b = (const float*)d_in[3];
    const float* cW1   = (const float*)d_in[4];
    const float* cb1   = (const float*)d_in[5];
    const float* cln1s = (const float*)d_in[6];
    const float* cln1b = (const float*)d_in[7];
    const float* cW2   = (const float*)d_in[8];
    const float* cb2   = (const float*)d_in[9];
    const float* cln2s = (const float*)d_in[10];
    const float* cln2b = (const float*)d_in[11];
    const float* m_in    = (const float*)d_in[12];
    const float* m_convK = (const float*)d_in[13];
    const float* m_convB = (const float*)d_in[14];
    const float* m_dtW   = (const float*)d_in[15];
    const float* m_dtB   = (const float*)d_in[16];
    const float* m_out   = (const float*)d_in[17];
    const float* proj_W  = (const float*)d_in[18];
    const float* proj_b  = (const float*)d_in[19];
    const float* norm_s  = (const float*)d_in[20];
    const float* norm_b  = (const float*)d_in[21];
    const float* outW    = (const float*)d_in[22];
    const float* outb    = (const float*)d_in[23];
    float* out = (float*)d_out;

    static float *p_h512=nullptr, *p_bufA=nullptr, *p_h=nullptr, *p_xz=nullptr,
                 *p_xc=nullptr, *p_dt=nullptr, *p_part=nullptr, *p_cat=nullptr,
                 *p_wpad=nullptr, *p_hout=nullptr;
    if (!p_h512) {
        cudaGetSymbolAddress((void**)&p_h512, g_h512);
        cudaGetSymbolAddress((void**)&p_bufA, g_bufA);
        cudaGetSymbolAddress((void**)&p_h,    g_h);
        cudaGetSymbolAddress((void**)&p_xz,   g_xz);
        cudaGetSymbolAddress((void**)&p_xc,   g_xc);
        cudaGetSymbolAddress((void**)&p_dt,   g_dt);
        cudaGetSymbolAddress((void**)&p_part, g_part);
        cudaGetSymbolAddress((void**)&p_cat,  g_cat);
        cudaGetSymbolAddress((void**)&p_wpad, g_wpad);
        cudaGetSymbolAddress((void**)&p_hout, g_hout);
        cudaFuncSetAttribute(tgemm_k, cudaFuncAttributeMaxDynamicSharedMemorySize,
                             SMEM_BYTES);
    }

    auto gemm = [&](const float* A, int lda, int arev,
                    const float* W, const float* bias,
                    const int* days, long wstride, int bstride,
                    float* C, int ldc, int coff, int crev,
                    int K, int N, int epi) {
        dim3 grid(N/BN, BT/BM);
        tgemm_k<<<grid, 256, SMEM_BYTES>>>(A, lda, arev, W, bias, days, wstride,
                                           bstride, C, ldc, coff, crev, K, N,
                                           epi, p_part);
    };

    // 1) adapter
    gemm(x, 512, 0, adapter_W, adapter_b, day_ids, 512L*512, 512,
         p_h512, 512, 0, 0, 512, 512, 1);
    // 2) stem
    gemm(p_h512, 512, 0, cW1, cb1, nullptr,0,0, p_bufA, 256, 0,0, 512, 256, 0);
    ln_k<<<BT/8, 256>>>(p_bufA, nullptr, cln1s, cln1b, p_h, 1);
    gemm(p_h, 256, 0, cW2, cb2, nullptr,0,0, p_bufA, 256, 0,0, 256, 256, 0);
    ln_k<<<BT/8, 256>>>(p_bufA, nullptr, cln2s, cln2b, p_h, 1);

    // 3) layers
    for (int l = 0; l < L_; ++l) {
        for (int dir = 0; dir < 2; ++dir) {
            int pi = l*2 + dir;
            const float* Win  = m_in    + (long)pi*256*1024;
            const float* ck   = m_convK + (long)pi*512*4;
            const float* cb   = m_convB + (long)pi*512;
            const float* dtW  = m_dtW   + (long)pi*512*512;
            const float* dtB  = m_dtB   + (long)pi*512;
            const float* Wout = m_out   + (long)pi*512*256;

            gemm(p_h, 256, dir, Win, nullptr, nullptr,0,0,
                 p_xz, 1024, 0, 0, 256, 1024, 0);
            conv_silu_k<<<(BT*128)/256, 256>>>(p_xz, ck, cb, p_xc);
            // dt GEMM with fused scan1 (epi=3 writes per-chunk sums to part)
            gemm(p_xc, 512, 0, dtW, dtB, nullptr,0,0,
                 p_dt, 512, 0, 0, 512, 512, 3);
            scan2_k<<<64, 256>>>(p_part);
            scan3_k<<<256, 256>>>(p_dt, p_xz, p_xc, p_part);
            gemm(p_xc, 512, 0, Wout, nullptr, nullptr,0,0,
                 p_cat, 512, dir*256, dir, 512, 256, 0);
        }
        gemm(p_cat, 512, 0, proj_W + (long)l*512*256, proj_b + l*256,
             nullptr,0,0, p_bufA, 256, 0,0, 512, 256, 0);
        ln_k<<<BT/8, 256>>>(p_bufA, p_h, norm_s + l*256, norm_b + l*256, p_h, 0);
    }

    // 4) head: pad W -> tensor GEMM -> log-softmax
    wpad_k<<<128, 256>>>(outW, p_wpad);
    gemm(p_h, 256, 0, p_wpad, nullptr, nullptr,0,0, p_hout, 128, 0,0, 256, 128, 0);
    lsm_k<<<BT/8, 256>>>(p_hout, outb, out);
}